// round 11
// baseline (speedup 1.0000x reference)
#include <cuda_runtime.h>

// Fixed problem shape
constexpr int B_  = 32;
constexpr int C_  = 256;
constexpr int N_  = 4608;         // 96*48
constexpr int N4  = N_ / 4;       // 1152
constexpr int N2  = N_ / 2;       // 2304

// Batch split: x chunk per split = 8 * 4.7 MB = 37.7 MB << L2
constexpr int SPLITS = 4;
constexpr int BH     = B_ / SPLITS;   // 8

// k1: float2 per thread, C split into 8 groups of 32 channels
constexpr int K1T       = 128;
constexpr int CH        = 8;
constexpr int CHC       = C_ / CH;    // 32
constexpr int NTM       = N2 / K1T;   // 18 tiles
constexpr int K1_UNROLL = 16;

// k3: 288 threads, 2 channels per block, ALL loads issued up-front
constexpr int K3T  = 288;
constexpr int K3R  = 2;
constexpr int K3IT = N4 / K3T;        // 4

// Scratch (__device__ globals: allocation-free rule)
__device__ float2   g_G[CH][B_ * N2];
__device__ float2   g_P[CH][B_ * N2];
__device__ float2   g_T[CH][B_ * N2];
__device__ float    g_theta[B_ * N_];
__device__ float    g_sp[B_ * NTM];
__device__ unsigned g_cnt[B_ * NTM];   // zero-init; self-resetting

// ---------------------------------------------------------------------------
// Kernel 1: partial dots over a 32-channel group (float2 per thread).
// Last-arriving block of each (b,tile) merges the CH partials (fixed-order
// math on identical data => deterministic).
// ---------------------------------------------------------------------------
__global__ __launch_bounds__(K1T)
void k1_dots(const float* __restrict__ x,
             const float* __restrict__ gw, const float* __restrict__ gb,
             const float* __restrict__ tw, const float* __restrict__ tb,
             const float* __restrict__ pw, const float* __restrict__ pb,
             int bbase)
{
    __shared__ float swt[3 * CHC];
    const int tid  = threadIdx.x;
    const int tile = blockIdx.x;
    const int ch   = blockIdx.y;
    const int b    = bbase + blockIdx.z;

    if (tid < CHC) {
        swt[tid]           = gw[ch * CHC + tid];
        swt[CHC + tid]     = tw[ch * CHC + tid];
        swt[2 * CHC + tid] = pw[ch * CHC + tid];
    }
    __syncthreads();

    const int n2 = tile * K1T + tid;
    const float2* xr = reinterpret_cast<const float2*>(x)
                       + ((size_t)b * C_ + (size_t)ch * CHC) * N2 + n2;

    float2 ga = make_float2(0.f, 0.f);
    float2 ta = make_float2(0.f, 0.f);
    float2 pa = make_float2(0.f, 0.f);

    #pragma unroll
    for (int c0 = 0; c0 < CHC; c0 += K1_UNROLL) {
        float2 xv[K1_UNROLL];
        #pragma unroll
        for (int j = 0; j < K1_UNROLL; j++)
            xv[j] = __ldg(xr + (size_t)(c0 + j) * N2);
        #pragma unroll
        for (int j = 0; j < K1_UNROLL; j++) {
            const int c = c0 + j;
            const float w0 = swt[c];
            const float w1 = swt[CHC + c];
            const float w2 = swt[2 * CHC + c];
            ga.x = fmaf(w0, xv[j].x, ga.x); ga.y = fmaf(w0, xv[j].y, ga.y);
            ta.x = fmaf(w1, xv[j].x, ta.x); ta.y = fmaf(w1, xv[j].y, ta.y);
            pa.x = fmaf(w2, xv[j].x, pa.x); pa.y = fmaf(w2, xv[j].y, pa.y);
        }
    }

    const size_t o = (size_t)b * N2 + n2;
    g_G[ch][o] = ga;
    g_T[ch][o] = ta;
    g_P[ch][o] = pa;

    // -------- last-arriver merge --------
    __threadfence();
    __syncthreads();
    __shared__ int sLast;
    if (tid == 0) {
        const int idx = b * NTM + tile;
        const unsigned old = atomicAdd(&g_cnt[idx], 1u);
        const int last = (old == CH - 1);
        if (last) g_cnt[idx] = 0;          // self-reset for next launch
        sLast = last;
    }
    __syncthreads();
    if (!sLast) return;

    const float gb0 = __ldg(gb), tb0 = __ldg(tb), pb0 = __ldg(pb);

    float2 G = make_float2(gb0, gb0);
    float2 P = make_float2(pb0, pb0);
    float2 T = make_float2(tb0, tb0);
    #pragma unroll
    for (int h = 0; h < CH; h++) {         // fixed order
        const float2 gv = g_G[h][o]; G.x += gv.x; G.y += gv.y;
        const float2 pv = g_P[h][o]; P.x += pv.x; P.y += pv.y;
        const float2 tv = g_T[h][o]; T.x += tv.x; T.y += tv.y;
    }
    reinterpret_cast<float2*>(g_theta)[o] = T;

    float pg = G.x * P.x + G.y * P.y;
    #pragma unroll
    for (int off = 16; off > 0; off >>= 1)
        pg += __shfl_xor_sync(0xffffffffu, pg, off);

    __shared__ float red[K1T / 32];
    if ((tid & 31) == 0) red[tid >> 5] = pg;
    __syncthreads();
    if (tid == 0) {
        float s = 0.f;
        #pragma unroll
        for (int w = 0; w < K1T / 32; w++) s += red[w];
        g_sp[b * NTM + tile] = s;
    }
}

// ---------------------------------------------------------------------------
// Kernel 3: z = theta[b,n]*ca[c] + cd[c] + x[b,c,n], 2 channels per block.
// ALL 12 float4 loads issued before any compute/store: per-thread MLP = 12
// so the ~230-cycle L2 hit latency is fully covered.
// ---------------------------------------------------------------------------
__global__ __launch_bounds__(K3T)
void k3_epilogue(const float* __restrict__ x, float* __restrict__ z,
                 const float* __restrict__ Ww, const float* __restrict__ Wb,
                 const float* __restrict__ gamma, const float* __restrict__ beta,
                 const float* __restrict__ mean,  const float* __restrict__ var,
                 int bbase)
{
    const int tid = threadIdx.x;
    const int cg  = blockIdx.x;               // 0..127
    const int b   = bbase + blockIdx.y;       // 8 batches

    float s = 0.f;
    #pragma unroll
    for (int t = 0; t < NTM; t++) s += g_sp[b * NTM + t];   // fixed order
    s *= (1.f / (float)N_);

    const int c0 = cg * K3R;
    const float inv0 = __ldg(gamma + c0)     * rsqrtf(__ldg(var + c0)     + 1e-5f);
    const float inv1 = __ldg(gamma + c0 + 1) * rsqrtf(__ldg(var + c0 + 1) + 1e-5f);
    const float ca0 = s * __ldg(Ww + c0)     * inv0;
    const float ca1 = s * __ldg(Ww + c0 + 1) * inv1;
    const float cd0 = (__ldg(Wb + c0)     - __ldg(mean + c0))     * inv0 + __ldg(beta + c0);
    const float cd1 = (__ldg(Wb + c0 + 1) - __ldg(mean + c0 + 1)) * inv1 + __ldg(beta + c0 + 1);

    const size_t row0 = ((size_t)b * C_ + c0) * N4;
    const float4* xr0 = reinterpret_cast<const float4*>(x) + row0;
    const float4* xr1 = xr0 + N4;
    float4*       zr0 = reinterpret_cast<float4*>(z) + row0;
    float4*       zr1 = zr0 + N4;
    const float4* th  = reinterpret_cast<const float4*>(g_theta) + (size_t)b * N4;

    // ---- issue ALL loads first (12 float4 in flight per thread) ----
    float4 tv[K3IT], av[K3IT], bv[K3IT];
    #pragma unroll
    for (int k = 0; k < K3IT; k++) {
        const int i = k * K3T + tid;
        tv[k] = __ldg(th + i);
        av[k] = __ldcs(xr0 + i);
        bv[k] = __ldcs(xr1 + i);
    }

    // ---- then compute + store ----
    #pragma unroll
    for (int k = 0; k < K3IT; k++) {
        const int i = k * K3T + tid;
        float4 o0, o1;
        o0.x = fmaf(tv[k].x, ca0, cd0) + av[k].x;
        o0.y = fmaf(tv[k].y, ca0, cd0) + av[k].y;
        o0.z = fmaf(tv[k].z, ca0, cd0) + av[k].z;
        o0.w = fmaf(tv[k].w, ca0, cd0) + av[k].w;
        __stcs(zr0 + i, o0);
        o1.x = fmaf(tv[k].x, ca1, cd1) + bv[k].x;
        o1.y = fmaf(tv[k].y, ca1, cd1) + bv[k].y;
        o1.z = fmaf(tv[k].z, ca1, cd1) + bv[k].z;
        o1.w = fmaf(tv[k].w, ca1, cd1) + bv[k].w;
        __stcs(zr1 + i, o1);
    }
}

// ---------------------------------------------------------------------------
extern "C" void kernel_launch(void* const* d_in, const int* in_sizes, int n_in,
                              void* d_out, int out_size)
{
    const float* x     = (const float*)d_in[0];
    const float* g_w   = (const float*)d_in[1];
    const float* g_b   = (const float*)d_in[2];
    const float* th_w  = (const float*)d_in[3];
    const float* th_b  = (const float*)d_in[4];
    const float* ph_w  = (const float*)d_in[5];
    const float* ph_b  = (const float*)d_in[6];
    const float* W_w   = (const float*)d_in[7];
    const float* W_b   = (const float*)d_in[8];
    const float* gamma = (const float*)d_in[9];
    const float* beta  = (const float*)d_in[10];
    const float* mean  = (const float*)d_in[11];
    const float* var   = (const float*)d_in[12];
    float* z = (float*)d_out;

    for (int h = 0; h < SPLITS; h++) {
        const int bbase = h * BH;
        dim3 g1(NTM, CH, BH);
        k1_dots<<<g1, K1T>>>(x, g_w, g_b, th_w, th_b, ph_w, ph_b, bbase);
        dim3 g3(C_ / K3R, BH);   // 128 x 8 = 1024 blocks
        k3_epilogue<<<g3, K3T>>>(x, z, W_w, W_b, gamma, beta, mean, var, bbase);
    }
}

// round 12
// speedup vs baseline: 1.1743x; 1.1743x over previous
#include <cuda_runtime.h>

// Fixed problem shape
constexpr int B_  = 32;
constexpr int C_  = 256;
constexpr int N_  = 4608;         // 96*48
constexpr int N4  = N_ / 4;       // 1152
constexpr int N2  = N_ / 2;       // 2304

// Batch split (R7 baseline config)
constexpr int SPLITS = 2;
constexpr int BH     = B_ / SPLITS;   // 16

// k1: float2 per thread, C split in quarters (exact R7 kernel)
constexpr int K1T       = 128;
constexpr int CH        = 4;
constexpr int CHC       = C_ / CH;    // 64
constexpr int NTM       = N2 / K1T;   // 18 tiles
constexpr int K1_UNROLL = 16;

// k3: 384 threads, 2 channels per block, ALL loads issued up-front
constexpr int K3T  = 384;
constexpr int K3R  = 2;
constexpr int K3IT = N4 / K3T;        // 3

// Scratch (__device__ globals: allocation-free rule)
__device__ float2   g_G[CH][B_ * N2];
__device__ float2   g_P[CH][B_ * N2];
__device__ float2   g_T[CH][B_ * N2];
__device__ float    g_theta[B_ * N_];
__device__ float    g_sp[B_ * NTM];
__device__ unsigned g_cnt[B_ * NTM];   // zero-init; self-resetting

// ---------------------------------------------------------------------------
// Kernel 1: partial dots over a 64-channel quarter (float2 per thread).
// Last-arriving block of each (b,tile) merges the CH partials (fixed-order
// math on identical data => deterministic). [unchanged from the 83.9 best]
// ---------------------------------------------------------------------------
__global__ __launch_bounds__(K1T)
void k1_dots(const float* __restrict__ x,
             const float* __restrict__ gw, const float* __restrict__ gb,
             const float* __restrict__ tw, const float* __restrict__ tb,
             const float* __restrict__ pw, const float* __restrict__ pb,
             int bbase)
{
    __shared__ float swt[3 * CHC];
    const int tid  = threadIdx.x;
    const int tile = blockIdx.x;
    const int ch   = blockIdx.y;
    const int b    = bbase + blockIdx.z;

    if (tid < CHC) {
        swt[tid]           = gw[ch * CHC + tid];
        swt[CHC + tid]     = tw[ch * CHC + tid];
        swt[2 * CHC + tid] = pw[ch * CHC + tid];
    }
    __syncthreads();

    const int n2 = tile * K1T + tid;
    const float2* xr = reinterpret_cast<const float2*>(x)
                       + ((size_t)b * C_ + (size_t)ch * CHC) * N2 + n2;

    float2 ga = make_float2(0.f, 0.f);
    float2 ta = make_float2(0.f, 0.f);
    float2 pa = make_float2(0.f, 0.f);

    #pragma unroll
    for (int c0 = 0; c0 < CHC; c0 += K1_UNROLL) {
        float2 xv[K1_UNROLL];
        #pragma unroll
        for (int j = 0; j < K1_UNROLL; j++)
            xv[j] = __ldg(xr + (size_t)(c0 + j) * N2);
        #pragma unroll
        for (int j = 0; j < K1_UNROLL; j++) {
            const int c = c0 + j;
            const float w0 = swt[c];
            const float w1 = swt[CHC + c];
            const float w2 = swt[2 * CHC + c];
            ga.x = fmaf(w0, xv[j].x, ga.x); ga.y = fmaf(w0, xv[j].y, ga.y);
            ta.x = fmaf(w1, xv[j].x, ta.x); ta.y = fmaf(w1, xv[j].y, ta.y);
            pa.x = fmaf(w2, xv[j].x, pa.x); pa.y = fmaf(w2, xv[j].y, pa.y);
        }
    }

    const size_t o = (size_t)b * N2 + n2;
    g_G[ch][o] = ga;
    g_T[ch][o] = ta;
    g_P[ch][o] = pa;

    // -------- last-arriver merge --------
    __threadfence();
    __syncthreads();
    __shared__ int sLast;
    if (tid == 0) {
        const int idx = b * NTM + tile;
        const unsigned old = atomicAdd(&g_cnt[idx], 1u);
        const int last = (old == CH - 1);
        if (last) g_cnt[idx] = 0;          // self-reset for next launch
        sLast = last;
    }
    __syncthreads();
    if (!sLast) return;

    const float gb0 = __ldg(gb), tb0 = __ldg(tb), pb0 = __ldg(pb);

    float2 G = make_float2(gb0, gb0);
    float2 P = make_float2(pb0, pb0);
    float2 T = make_float2(tb0, tb0);
    #pragma unroll
    for (int h = 0; h < CH; h++) {         // fixed order
        const float2 gv = g_G[h][o]; G.x += gv.x; G.y += gv.y;
        const float2 pv = g_P[h][o]; P.x += pv.x; P.y += pv.y;
        const float2 tv = g_T[h][o]; T.x += tv.x; T.y += tv.y;
    }
    reinterpret_cast<float2*>(g_theta)[o] = T;

    float pg = G.x * P.x + G.y * P.y;
    #pragma unroll
    for (int off = 16; off > 0; off >>= 1)
        pg += __shfl_xor_sync(0xffffffffu, pg, off);

    __shared__ float red[K1T / 32];
    if ((tid & 31) == 0) red[tid >> 5] = pg;
    __syncthreads();
    if (tid == 0) {
        float s = 0.f;
        #pragma unroll
        for (int w = 0; w < K1T / 32; w++) s += red[w];
        g_sp[b * NTM + tile] = s;
    }
}

// ---------------------------------------------------------------------------
// Kernel 3: z = theta*ca + cd + x, 2 channels per block, 384 threads.
// ALL 9 float4 loads issued before any compute/store (MLP = 9 per thread)
// to cover the ~577-cycle DRAM read latency. theta shared across both rows.
// ---------------------------------------------------------------------------
__global__ __launch_bounds__(K3T)
void k3_epilogue(const float* __restrict__ x, float* __restrict__ z,
                 const float* __restrict__ Ww, const float* __restrict__ Wb,
                 const float* __restrict__ gamma, const float* __restrict__ beta,
                 const float* __restrict__ mean,  const float* __restrict__ var,
                 int bbase)
{
    const int tid = threadIdx.x;
    const int cg  = blockIdx.x;               // 0..127
    const int b   = bbase + blockIdx.y;

    float s = 0.f;
    #pragma unroll
    for (int t = 0; t < NTM; t++) s += g_sp[b * NTM + t];   // fixed order
    s *= (1.f / (float)N_);

    const int c0 = cg * K3R;
    const float inv0 = __ldg(gamma + c0)     * rsqrtf(__ldg(var + c0)     + 1e-5f);
    const float inv1 = __ldg(gamma + c0 + 1) * rsqrtf(__ldg(var + c0 + 1) + 1e-5f);
    const float ca0 = s * __ldg(Ww + c0)     * inv0;
    const float ca1 = s * __ldg(Ww + c0 + 1) * inv1;
    const float cd0 = (__ldg(Wb + c0)     - __ldg(mean + c0))     * inv0 + __ldg(beta + c0);
    const float cd1 = (__ldg(Wb + c0 + 1) - __ldg(mean + c0 + 1)) * inv1 + __ldg(beta + c0 + 1);

    const size_t row0 = ((size_t)b * C_ + c0) * N4;
    const float4* xr0 = reinterpret_cast<const float4*>(x) + row0;
    const float4* xr1 = xr0 + N4;
    float4*       zr0 = reinterpret_cast<float4*>(z) + row0;
    float4*       zr1 = zr0 + N4;
    const float4* th  = reinterpret_cast<const float4*>(g_theta) + (size_t)b * N4;

    // ---- issue ALL loads first (9 float4 in flight per thread) ----
    float4 tv[K3IT], av[K3IT], bv[K3IT];
    #pragma unroll
    for (int k = 0; k < K3IT; k++) {
        const int i = k * K3T + tid;
        tv[k] = __ldg(th + i);
        av[k] = __ldcs(xr0 + i);
        bv[k] = __ldcs(xr1 + i);
    }

    // ---- then compute + store ----
    #pragma unroll
    for (int k = 0; k < K3IT; k++) {
        const int i = k * K3T + tid;
        float4 o0, o1;
        o0.x = fmaf(tv[k].x, ca0, cd0) + av[k].x;
        o0.y = fmaf(tv[k].y, ca0, cd0) + av[k].y;
        o0.z = fmaf(tv[k].z, ca0, cd0) + av[k].z;
        o0.w = fmaf(tv[k].w, ca0, cd0) + av[k].w;
        __stcs(zr0 + i, o0);
        o1.x = fmaf(tv[k].x, ca1, cd1) + bv[k].x;
        o1.y = fmaf(tv[k].y, ca1, cd1) + bv[k].y;
        o1.z = fmaf(tv[k].z, ca1, cd1) + bv[k].z;
        o1.w = fmaf(tv[k].w, ca1, cd1) + bv[k].w;
        __stcs(zr1 + i, o1);
    }
}

// ---------------------------------------------------------------------------
extern "C" void kernel_launch(void* const* d_in, const int* in_sizes, int n_in,
                              void* d_out, int out_size)
{
    const float* x     = (const float*)d_in[0];
    const float* g_w   = (const float*)d_in[1];
    const float* g_b   = (const float*)d_in[2];
    const float* th_w  = (const float*)d_in[3];
    const float* th_b  = (const float*)d_in[4];
    const float* ph_w  = (const float*)d_in[5];
    const float* ph_b  = (const float*)d_in[6];
    const float* W_w   = (const float*)d_in[7];
    const float* W_b   = (const float*)d_in[8];
    const float* gamma = (const float*)d_in[9];
    const float* beta  = (const float*)d_in[10];
    const float* mean  = (const float*)d_in[11];
    const float* var   = (const float*)d_in[12];
    float* z = (float*)d_out;

    for (int h = 0; h < SPLITS; h++) {
        const int bbase = h * BH;
        dim3 g1(NTM, CH, BH);
        k1_dots<<<g1, K1T>>>(x, g_w, g_b, th_w, th_b, ph_w, ph_b, bbase);
        dim3 g3(C_ / K3R, BH);   // 128 x 16 = 2048 blocks
        k3_epilogue<<<g3, K3T>>>(x, z, W_w, W_b, gamma, beta, mean, var, bbase);
    }
}